// round 7
// baseline (speedup 1.0000x reference)
#include <cuda_runtime.h>
#include <cuda_bf16.h>
#include <math.h>

// Problem constants (dataset-fixed; scratch capacity)
#define N_NODES 50000
#define DIM     64
#define N_EDGES 1600000

// ---------------------------------------------------------------------------
// Scratch (device globals — no allocation allowed)
// ---------------------------------------------------------------------------
__device__ float4 g_acc4[N_NODES * (DIM / 4)];   // 12.8 MB accumulator
__device__ float  g_p[N_NODES];                  // feat[i] . lin_w[0:64]
__device__ float  g_q[N_NODES];                  // feat[i] . lin_w[64:128]
__device__ int    g_has[N_NODES];                // in-degree > 0 flag

// ---------------------------------------------------------------------------
// Kernel 1: fused init + per-node attention pre-dots.
// One warp per node: zero acc row + has flag, compute
//   p[i] = feat[i] . lin_w[0:64],  q[i] = feat[i] . lin_w[64:128]
// ---------------------------------------------------------------------------
__global__ void __launch_bounds__(256)
init_pq_kernel(const float* __restrict__ feat,
               const float* __restrict__ lin_w,
               int n_nodes) {
    int wid  = (blockIdx.x * blockDim.x + threadIdx.x) >> 5;
    int lane = threadIdx.x & 31;
    if (wid >= n_nodes) return;

    if (lane < 16) {
        g_acc4[wid * 16 + lane] = make_float4(0.f, 0.f, 0.f, 0.f);
    }
    if (lane == 16) {
        g_has[wid] = 0;
    }

    float f0 = feat[wid * DIM + lane];
    float f1 = feat[wid * DIM + lane + 32];
    float pv = f0 * lin_w[lane]      + f1 * lin_w[lane + 32];
    float qv = f0 * lin_w[64 + lane] + f1 * lin_w[96 + lane];

    #pragma unroll
    for (int off = 16; off > 0; off >>= 1) {
        pv += __shfl_xor_sync(0xffffffffu, pv, off);
        qv += __shfl_xor_sync(0xffffffffu, qv, off);
    }
    if (lane == 0) {
        g_p[wid] = pv;
        g_q[wid] = qv;
    }
}

// ---------------------------------------------------------------------------
// Kernel 2: edge scatter. 8 lanes per edge, 2 float4 chunks per lane (MLP=2).
// acc[dst] += sigmoid(relu(p[src]+q[dst]+b)) * feat[src]
// ---------------------------------------------------------------------------
__device__ __forceinline__ void red_add_f4(float4* addr, float4 v) {
    asm volatile("red.global.add.v4.f32 [%0], {%1,%2,%3,%4};"
                 :: "l"(addr), "f"(v.x), "f"(v.y), "f"(v.z), "f"(v.w)
                 : "memory");
}

__global__ void __launch_bounds__(256)
edge_scatter_kernel(const int* __restrict__ esrc,
                    const int* __restrict__ edst,
                    const float4* __restrict__ feat4,
                    const float* __restrict__ lin_b,
                    int n_edges) {
    int tid = blockIdx.x * blockDim.x + threadIdx.x;
    int e = tid >> 3;           // edge index (8 lanes per edge)
    if (e >= n_edges) return;
    int c = tid & 7;            // chunk pair id: handles float4 chunks c and c+8
    int lane = threadIdx.x & 31;

    int s = 0, d = 0;
    float a = 0.f;
    if (c == 0) {               // lanes 0,8,16,24 are group leaders
        s = esrc[e];
        d = edst[e];
        float x = g_p[s] + g_q[d] + lin_b[0];
        float r = fmaxf(x, 0.f);
        a = 1.f / (1.f + expf(-r));   // precise expf: off critical path, 4/warp
    }
    int srclane = lane & 24;    // leader lane of this 8-lane group
    s = __shfl_sync(0xffffffffu, s, srclane);
    d = __shfl_sync(0xffffffffu, d, srclane);
    a = __shfl_sync(0xffffffffu, a, srclane);

    // two independent gather loads (MLP=2), then two REDGs
    float4 v0 = feat4[s * 16 + c];
    float4 v1 = feat4[s * 16 + c + 8];
    float4 w0 = make_float4(v0.x * a, v0.y * a, v0.z * a, v0.w * a);
    float4 w1 = make_float4(v1.x * a, v1.y * a, v1.z * a, v1.w * a);
    red_add_f4(&g_acc4[d * 16 + c],     w0);
    red_add_f4(&g_acc4[d * 16 + c + 8], w1);
    if (c == 0) g_has[d] = 1;   // benign race: all writers store 1
}

// ---------------------------------------------------------------------------
// Kernel 3: finalize.
//   has : out = tanh( (acc @ W_rel) * norm + feat @ loop_w )
//   !has: out = tanh(  feat * norm         + feat @ evolve_loop_w )
// 64 threads per node (thread j owns output column j); 4 nodes per 256-thr block.
// ---------------------------------------------------------------------------
__global__ void __launch_bounds__(256)
finalize_kernel(const float* __restrict__ feat,
                const float* __restrict__ norm,
                const float* __restrict__ W_rel,
                const float* __restrict__ loop_w,
                const float* __restrict__ evolve_w,
                float* __restrict__ out,
                int n_nodes) {
    __shared__ float sW0[DIM * DIM];   // W_rel
    __shared__ float sWl[DIM * DIM];   // loop_w
    __shared__ float sF[4][DIM];       // staged feat rows
    __shared__ float sA[4][DIM];       // staged acc rows

    for (int i = threadIdx.x; i < DIM * DIM; i += blockDim.x) {
        sW0[i] = W_rel[i];
        sWl[i] = loop_w[i];
    }
    __syncthreads();

    int gr = threadIdx.x >> 6;    // group within block: 0..3
    int j  = threadIdx.x & 63;    // output column
    int gstride = gridDim.x * 4;
    int g0 = blockIdx.x * 4 + gr;
    int iters = (n_nodes + gstride - 1) / gstride;
    const float* accf = (const float*)g_acc4;

    for (int it = 0; it < iters; it++) {
        int i = g0 + it * gstride;
        __syncthreads();                      // protect smem reuse across iters
        if (i < n_nodes) {
            sF[gr][j] = feat[i * DIM + j];
            sA[gr][j] = accf[i * DIM + j];
        }
        __syncthreads();
        if (i < n_nodes) {
            bool has = (g_has[i] != 0);
            float accv = 0.f, loopv = 0.f;
            if (has) {
                #pragma unroll
                for (int k = 0; k < DIM; k++) {
                    accv  = fmaf(sA[gr][k], sW0[k * DIM + j], accv);
                    loopv = fmaf(sF[gr][k], sWl[k * DIM + j], loopv);
                }
            } else {
                #pragma unroll 8
                for (int k = 0; k < DIM; k++) {
                    loopv = fmaf(sF[gr][k], evolve_w[k * DIM + j], loopv);
                }
            }
            float nrm = norm[i];
            float nf = has ? accv * nrm : sF[gr][j] * nrm;
            out[i * DIM + j] = tanhf(nf + loopv);
        }
    }
}

// ---------------------------------------------------------------------------
// Launch
// Inputs (metadata order): feat, norm, edge_src, edge_dst, etype,
//                          W_rel, lin_w, lin_b, loop_w, evolve_loop_w
// ---------------------------------------------------------------------------
extern "C" void kernel_launch(void* const* d_in, const int* in_sizes, int n_in,
                              void* d_out, int out_size) {
    const float* feat     = (const float*)d_in[0];
    const float* norm     = (const float*)d_in[1];
    const int*   edge_src = (const int*)  d_in[2];
    const int*   edge_dst = (const int*)  d_in[3];
    // d_in[4] = etype: unused (reference applies same W_rel to every type)
    const float* W_rel    = (const float*)d_in[5];
    const float* lin_w    = (const float*)d_in[6];
    const float* lin_b    = (const float*)d_in[7];
    const float* loop_w   = (const float*)d_in[8];
    const float* evolve_w = (const float*)d_in[9];
    float*       out      = (float*)d_out;

    int n_nodes = in_sizes[1];                 // norm has N elements
    int n_edges = in_sizes[2];                 // edge_src has E elements
    if (n_nodes > N_NODES) n_nodes = N_NODES;  // scratch capacity clamp
    if (n_edges > N_EDGES) n_edges = N_EDGES;

    // 1) fused init + per-node attention dots: one warp per node
    {
        long long threads = (long long)n_nodes * 32;
        init_pq_kernel<<<(int)((threads + 255) / 256), 256>>>(feat, lin_w, n_nodes);
    }
    // 2) edge scatter: 8 threads per edge
    {
        long long threads = (long long)n_edges * 8;
        edge_scatter_kernel<<<(int)((threads + 255) / 256), 256>>>(
            edge_src, edge_dst, (const float4*)feat, lin_b, n_edges);
    }
    // 3) finalize: 912 blocks (152 SMs x 6 resident at 34KB smem), grid-stride
    finalize_kernel<<<912, 256>>>(feat, norm, W_rel, loop_w, evolve_w, out, n_nodes);
}

// round 9
// speedup vs baseline: 1.0546x; 1.0546x over previous
#include <cuda_runtime.h>
#include <cuda_bf16.h>
#include <math.h>

// Problem constants (dataset-fixed; scratch capacity)
#define N_NODES 50000
#define DIM     64
#define N_EDGES 1600000
#define SCAN_B  512
#define MAX_SB  128     // max scan blocks: ceil(50000/512)=98

// ---------------------------------------------------------------------------
// Scratch (device globals — no allocation allowed)
// ---------------------------------------------------------------------------
__device__ float4 g_acc4[N_NODES * (DIM / 4)];   // 12.8 MB accumulator
__device__ float  g_p[N_NODES];                  // feat[i] . lin_w[0:64]
__device__ float  g_q[N_NODES];                  // feat[i] . lin_w[64:128]
__device__ int    g_deg[N_NODES];                // in-degree (histogram)
__device__ int    g_offsets[N_NODES + 1];        // CSR row offsets (by dst)
__device__ int    g_cursor[N_NODES];             // bump cursors for build
__device__ int    g_blocksum[MAX_SB];            // scan partials
__device__ int    g_blockoff[MAX_SB];
__device__ int    g_csr_src[N_EDGES];            // src ids sorted by dst (6.4 MB)

// ---------------------------------------------------------------------------
// Kernel 1: zero deg + per-node attention pre-dots. One warp per node.
// ---------------------------------------------------------------------------
__global__ void __launch_bounds__(256)
init_pq_kernel(const float* __restrict__ feat,
               const float* __restrict__ lin_w,
               int n_nodes) {
    int wid  = (blockIdx.x * blockDim.x + threadIdx.x) >> 5;
    int lane = threadIdx.x & 31;
    if (wid >= n_nodes) return;

    if (lane == 1) g_deg[wid] = 0;

    float f0 = feat[wid * DIM + lane];
    float f1 = feat[wid * DIM + lane + 32];
    float pv = f0 * lin_w[lane]      + f1 * lin_w[lane + 32];
    float qv = f0 * lin_w[64 + lane] + f1 * lin_w[96 + lane];

    #pragma unroll
    for (int off = 16; off > 0; off >>= 1) {
        pv += __shfl_xor_sync(0xffffffffu, pv, off);
        qv += __shfl_xor_sync(0xffffffffu, qv, off);
    }
    if (lane == 0) {
        g_p[wid] = pv;
        g_q[wid] = qv;
    }
}

// ---------------------------------------------------------------------------
// Kernel 2: in-degree histogram.
// ---------------------------------------------------------------------------
__global__ void __launch_bounds__(256)
hist_kernel(const int* __restrict__ edst, int n_edges) {
    int e = blockIdx.x * blockDim.x + threadIdx.x;
    if (e < n_edges) atomicAdd(&g_deg[edst[e]], 1);
}

// ---------------------------------------------------------------------------
// Kernels 3a/3b/3c: exclusive scan of g_deg into g_offsets (+ cursor copy).
// ---------------------------------------------------------------------------
__global__ void __launch_bounds__(SCAN_B)
scan1_kernel(int n_nodes) {
    __shared__ int tmp[SCAN_B];
    int i = blockIdx.x * SCAN_B + threadIdx.x;
    int v = (i < n_nodes) ? g_deg[i] : 0;
    tmp[threadIdx.x] = v;
    __syncthreads();
    #pragma unroll
    for (int off = 1; off < SCAN_B; off <<= 1) {
        int t = (threadIdx.x >= off) ? tmp[threadIdx.x - off] : 0;
        __syncthreads();
        tmp[threadIdx.x] += t;
        __syncthreads();
    }
    if (i < n_nodes) g_offsets[i] = tmp[threadIdx.x] - v;   // exclusive partial
    if (threadIdx.x == SCAN_B - 1) g_blocksum[blockIdx.x] = tmp[SCAN_B - 1];
}

__global__ void __launch_bounds__(MAX_SB)
scan2_kernel(int n_blocks) {
    __shared__ int s[MAX_SB];
    if (threadIdx.x < n_blocks) s[threadIdx.x] = g_blocksum[threadIdx.x];
    __syncthreads();
    if (threadIdx.x == 0) {
        int run = 0;
        for (int i = 0; i < n_blocks; i++) { int t = s[i]; s[i] = run; run += t; }
    }
    __syncthreads();
    if (threadIdx.x < n_blocks) g_blockoff[threadIdx.x] = s[threadIdx.x];
}

__global__ void __launch_bounds__(SCAN_B)
scan3_kernel(int n_nodes, int n_edges) {
    int i = blockIdx.x * SCAN_B + threadIdx.x;
    if (i < n_nodes) {
        int off = g_offsets[i] + g_blockoff[blockIdx.x];
        g_offsets[i] = off;
        g_cursor[i]  = off;
    }
    if (i == 0) g_offsets[n_nodes] = n_edges;
}

// ---------------------------------------------------------------------------
// Kernel 4: CSR build — scatter src ids into dst-sorted order.
// ---------------------------------------------------------------------------
__global__ void __launch_bounds__(256)
build_kernel(const int* __restrict__ esrc, const int* __restrict__ edst,
             int n_edges) {
    int e = blockIdx.x * blockDim.x + threadIdx.x;
    if (e < n_edges) {
        int d = edst[e];
        int pos = atomicAdd(&g_cursor[d], 1);
        g_csr_src[pos] = esrc[e];
    }
}

// ---------------------------------------------------------------------------
// Kernel 5: gather. One warp per node, grid-stride.
//   acc[i] = sum_{e: dst=i} sigmoid(relu(p[src]+q[i]+b)) * feat[src]
// Lane owns float2 of the 64-dim accumulator. 32-edge chunks: coalesced src
// load, per-lane attention (one MUFU/lane/chunk), shuffle-broadcast inner loop
// with 32 independent feat gathers (deep MLP).
// ---------------------------------------------------------------------------
__global__ void __launch_bounds__(256)
gather_kernel(const float2* __restrict__ feat2,
              const float* __restrict__ lin_b,
              int n_nodes) {
    int warp  = (blockIdx.x * blockDim.x + threadIdx.x) >> 5;
    int lane  = threadIdx.x & 31;
    int nwarp = (gridDim.x * blockDim.x) >> 5;
    float b = lin_b[0];

    for (int i = warp; i < n_nodes; i += nwarp) {
        int off = g_offsets[i];
        int end = g_offsets[i + 1];
        float qd = g_q[i] + b;
        float ax = 0.f, ay = 0.f;

        for (int base = off; base < end; base += 32) {
            int cnt = end - base;
            if (cnt > 32) cnt = 32;
            int  e_ok = (lane < cnt);
            int  s_l  = e_ok ? g_csr_src[base + lane] : 0;
            float p_l = e_ok ? g_p[s_l] : 0.f;
            float x   = fmaxf(p_l + qd, 0.f);
            float a_l = 1.f / (1.f + __expf(-x));

            #pragma unroll 4
            for (int j = 0; j < cnt; j++) {
                int   s = __shfl_sync(0xffffffffu, s_l, j);
                float a = __shfl_sync(0xffffffffu, a_l, j);
                float2 v = feat2[s * 32 + lane];
                ax = fmaf(a, v.x, ax);
                ay = fmaf(a, v.y, ay);
            }
        }
        ((float2*)g_acc4)[i * 32 + lane] = make_float2(ax, ay);
    }
}

// ---------------------------------------------------------------------------
// Kernel 6: finalize (unchanged math; has = deg>0).
// ---------------------------------------------------------------------------
__global__ void __launch_bounds__(256)
finalize_kernel(const float* __restrict__ feat,
                const float* __restrict__ norm,
                const float* __restrict__ W_rel,
                const float* __restrict__ loop_w,
                const float* __restrict__ evolve_w,
                float* __restrict__ out,
                int n_nodes) {
    __shared__ float sW0[DIM * DIM];
    __shared__ float sWl[DIM * DIM];
    __shared__ float sF[4][DIM];
    __shared__ float sA[4][DIM];

    for (int i = threadIdx.x; i < DIM * DIM; i += blockDim.x) {
        sW0[i] = W_rel[i];
        sWl[i] = loop_w[i];
    }
    __syncthreads();

    int gr = threadIdx.x >> 6;
    int j  = threadIdx.x & 63;
    int gstride = gridDim.x * 4;
    int g0 = blockIdx.x * 4 + gr;
    int iters = (n_nodes + gstride - 1) / gstride;
    const float* accf = (const float*)g_acc4;

    for (int it = 0; it < iters; it++) {
        int i = g0 + it * gstride;
        __syncthreads();
        if (i < n_nodes) {
            sF[gr][j] = feat[i * DIM + j];
            sA[gr][j] = accf[i * DIM + j];
        }
        __syncthreads();
        if (i < n_nodes) {
            bool has = (g_deg[i] > 0);
            float accv = 0.f, loopv = 0.f;
            if (has) {
                #pragma unroll
                for (int k = 0; k < DIM; k++) {
                    accv  = fmaf(sA[gr][k], sW0[k * DIM + j], accv);
                    loopv = fmaf(sF[gr][k], sWl[k * DIM + j], loopv);
                }
            } else {
                #pragma unroll 8
                for (int k = 0; k < DIM; k++) {
                    loopv = fmaf(sF[gr][k], evolve_w[k * DIM + j], loopv);
                }
            }
            float nrm = norm[i];
            float nf = has ? accv * nrm : sF[gr][j] * nrm;
            out[i * DIM + j] = tanhf(nf + loopv);
        }
    }
}

// ---------------------------------------------------------------------------
// Launch
// Inputs (metadata order): feat, norm, edge_src, edge_dst, etype,
//                          W_rel, lin_w, lin_b, loop_w, evolve_loop_w
// ---------------------------------------------------------------------------
extern "C" void kernel_launch(void* const* d_in, const int* in_sizes, int n_in,
                              void* d_out, int out_size) {
    const float* feat     = (const float*)d_in[0];
    const float* norm     = (const float*)d_in[1];
    const int*   edge_src = (const int*)  d_in[2];
    const int*   edge_dst = (const int*)  d_in[3];
    // d_in[4] = etype: unused (same W_rel for every type)
    const float* W_rel    = (const float*)d_in[5];
    const float* lin_w    = (const float*)d_in[6];
    const float* lin_b    = (const float*)d_in[7];
    const float* loop_w   = (const float*)d_in[8];
    const float* evolve_w = (const float*)d_in[9];
    float*       out      = (float*)d_out;

    int n_nodes = in_sizes[1];
    int n_edges = in_sizes[2];
    if (n_nodes > N_NODES) n_nodes = N_NODES;
    if (n_edges > N_EDGES) n_edges = N_EDGES;

    int eb = (n_edges + 255) / 256;
    int sb = (n_nodes + SCAN_B - 1) / SCAN_B;      // scan blocks (98)

    // 1) zero deg + per-node attention dots (one warp per node)
    init_pq_kernel<<<(n_nodes * 32 + 255) / 256, 256>>>(feat, lin_w, n_nodes);
    // 2) in-degree histogram
    hist_kernel<<<eb, 256>>>(edge_dst, n_edges);
    // 3) exclusive scan -> offsets + cursor
    scan1_kernel<<<sb, SCAN_B>>>(n_nodes);
    scan2_kernel<<<1, MAX_SB>>>(sb);
    scan3_kernel<<<sb, SCAN_B>>>(n_nodes, n_edges);
    // 4) CSR build (src ids grouped by dst)
    build_kernel<<<eb, 256>>>(edge_src, edge_dst, n_edges);
    // 5) gather: warp per node, grid-stride (1216 blocks = 9728 warps)
    gather_kernel<<<1216, 256>>>((const float2*)feat, lin_b, n_nodes);
    // 6) finalize
    finalize_kernel<<<912, 256>>>(feat, norm, W_rel, loop_w, evolve_w, out, n_nodes);
}

// round 10
// speedup vs baseline: 1.1848x; 1.1235x over previous
#include <cuda_runtime.h>
#include <cuda_bf16.h>
#include <math.h>

// Problem constants (dataset-fixed; scratch capacity)
#define N_NODES 50000
#define DIM     64
#define N_EDGES 1600000
#define SCAN_B  512

// ---------------------------------------------------------------------------
// Scratch (device globals — no allocation allowed; zero-init at module load)
// ---------------------------------------------------------------------------
__device__ float4 g_acc4[N_NODES * (DIM / 4)];   // 12.8 MB accumulator
__device__ float  g_p[N_NODES];                  // feat[i] . lin_w[0:64]
__device__ float  g_q[N_NODES];                  // feat[i] . lin_w[64:128]
__device__ int    g_deg[N_NODES];                // in-degree (must be 0 at entry;
                                                 // zeroed by build_kernel for replays)
__device__ int    g_offsets[N_NODES + 1];        // CSR row offsets (by dst)
__device__ int    g_cursor[N_NODES];             // bump cursors for build
__device__ int    g_csr_src[N_EDGES];            // src ids sorted by dst (6.4 MB)

// ---------------------------------------------------------------------------
// Kernel 1: fused per-node pq dots + in-degree histogram (grid split).
//   blocks [0, pq_blocks)       : one warp per node -> p, q
//   blocks [pq_blocks, end)     : edge-parallel histogram into g_deg
// ---------------------------------------------------------------------------
__global__ void __launch_bounds__(256)
pq_hist_kernel(const float* __restrict__ feat,
               const float* __restrict__ lin_w,
               const int* __restrict__ edst,
               int n_nodes, int n_edges, int pq_blocks) {
    if ((int)blockIdx.x < pq_blocks) {
        int wid  = (blockIdx.x * blockDim.x + threadIdx.x) >> 5;
        int lane = threadIdx.x & 31;
        if (wid >= n_nodes) return;

        float f0 = feat[wid * DIM + lane];
        float f1 = feat[wid * DIM + lane + 32];
        float pv = f0 * lin_w[lane]      + f1 * lin_w[lane + 32];
        float qv = f0 * lin_w[64 + lane] + f1 * lin_w[96 + lane];

        #pragma unroll
        for (int off = 16; off > 0; off >>= 1) {
            pv += __shfl_xor_sync(0xffffffffu, pv, off);
            qv += __shfl_xor_sync(0xffffffffu, qv, off);
        }
        if (lane == 0) {
            g_p[wid] = pv;
            g_q[wid] = qv;
        }
    } else {
        int e = (blockIdx.x - pq_blocks) * blockDim.x + threadIdx.x;
        if (e < n_edges) atomicAdd(&g_deg[edst[e]], 1);
    }
}

// ---------------------------------------------------------------------------
// Kernel 2: single-launch exclusive scan.
// Block b redundantly sums deg[0 .. b*SCAN_B) for its base (cheap: <=50K ints),
// then scans its own tile. Writes offsets + cursor. deg left intact (zeroed
// later by build_kernel).
// ---------------------------------------------------------------------------
__global__ void __launch_bounds__(SCAN_B)
fullscan_kernel(int n_nodes, int n_edges) {
    __shared__ int tile[SCAN_B];
    __shared__ int wsum[SCAN_B / 32];
    __shared__ int sbase;

    int t     = threadIdx.x;
    int lane  = t & 31;
    int wid   = t >> 5;
    int start = blockIdx.x * SCAN_B;

    // base = sum of deg[0 .. start)
    int part = 0;
    for (int i = t; i < start; i += SCAN_B) part += g_deg[i];
    #pragma unroll
    for (int off = 16; off > 0; off >>= 1)
        part += __shfl_xor_sync(0xffffffffu, part, off);
    if (lane == 0) wsum[wid] = part;
    __syncthreads();
    if (t == 0) {
        int s = 0;
        #pragma unroll
        for (int w = 0; w < SCAN_B / 32; w++) s += wsum[w];
        sbase = s;
    }

    // in-tile inclusive scan (Hillis-Steele)
    int v = (start + t < n_nodes) ? g_deg[start + t] : 0;
    tile[t] = v;
    __syncthreads();
    #pragma unroll
    for (int off = 1; off < SCAN_B; off <<= 1) {
        int tv = (t >= off) ? tile[t - off] : 0;
        __syncthreads();
        tile[t] += tv;
        __syncthreads();
    }
    int off_val = sbase + tile[t] - v;   // exclusive
    if (start + t < n_nodes) {
        g_offsets[start + t] = off_val;
        g_cursor[start + t]  = off_val;
    }
    if (start + t == 0) g_offsets[n_nodes] = n_edges;
}

// ---------------------------------------------------------------------------
// Kernel 3: CSR build — scatter src ids into dst-sorted order.
// Also re-zeros g_deg (dead after scan) so the next graph replay starts clean.
// ---------------------------------------------------------------------------
__global__ void __launch_bounds__(256)
build_kernel(const int* __restrict__ esrc, const int* __restrict__ edst,
             int n_edges, int n_nodes) {
    int e = blockIdx.x * blockDim.x + threadIdx.x;
    if (e < n_nodes) g_deg[e] = 0;     // n_edges >= n_nodes here
    if (e < n_edges) {
        int d = edst[e];
        int pos = atomicAdd(&g_cursor[d], 1);
        g_csr_src[pos] = esrc[e];
    }
}

// ---------------------------------------------------------------------------
// Kernel 4: gather. One warp per node, grid-stride.
//   acc[i] = sum_{e: dst=i} sigmoid(relu(p[src]+q[i]+b)) * feat[src]
// ---------------------------------------------------------------------------
__global__ void __launch_bounds__(256)
gather_kernel(const float2* __restrict__ feat2,
              const float* __restrict__ lin_b,
              int n_nodes) {
    int warp  = (blockIdx.x * blockDim.x + threadIdx.x) >> 5;
    int lane  = threadIdx.x & 31;
    int nwarp = (gridDim.x * blockDim.x) >> 5;
    float b = lin_b[0];

    for (int i = warp; i < n_nodes; i += nwarp) {
        int off = g_offsets[i];
        int end = g_offsets[i + 1];
        float qd = g_q[i] + b;
        float ax = 0.f, ay = 0.f;

        for (int base = off; base < end; base += 32) {
            int cnt = end - base;
            if (cnt > 32) cnt = 32;
            int  e_ok = (lane < cnt);
            int  s_l  = e_ok ? g_csr_src[base + lane] : 0;
            float p_l = e_ok ? g_p[s_l] : 0.f;
            float x   = fmaxf(p_l + qd, 0.f);
            float a_l = 1.f / (1.f + __expf(-x));

            #pragma unroll 4
            for (int j = 0; j < cnt; j++) {
                int   s = __shfl_sync(0xffffffffu, s_l, j);
                float a = __shfl_sync(0xffffffffu, a_l, j);
                float2 v = feat2[s * 32 + lane];
                ax = fmaf(a, v.x, ax);
                ay = fmaf(a, v.y, ay);
            }
        }
        ((float2*)g_acc4)[i * 32 + lane] = make_float2(ax, ay);
    }
}

// ---------------------------------------------------------------------------
// Kernel 5: finalize with weight columns in REGISTERS.
// Thread j holds W_rel[:,j] (64 regs) + loop_w[:,j] (64 regs), statically
// indexed via full unroll. Only sA/sF broadcasts go through smem (float4).
// 128 threads/block = 2 nodes per iteration; has = offsets[i+1] > offsets[i].
// ---------------------------------------------------------------------------
__global__ void __launch_bounds__(128)
finalize_kernel(const float* __restrict__ feat,
                const float* __restrict__ norm,
                const float* __restrict__ W_rel,
                const float* __restrict__ loop_w,
                const float* __restrict__ evolve_w,
                float* __restrict__ out,
                int n_nodes) {
    __shared__ float4 sF4[2][DIM / 4];
    __shared__ float4 sA4[2][DIM / 4];

    int j  = threadIdx.x & 63;
    int gr = threadIdx.x >> 6;          // 0..1

    float wr[DIM], wl[DIM];
    #pragma unroll
    for (int k = 0; k < DIM; k++) wr[k] = W_rel[k * DIM + j];
    #pragma unroll
    for (int k = 0; k < DIM; k++) wl[k] = loop_w[k * DIM + j];

    const float* accf = (const float*)g_acc4;
    int gstride = gridDim.x * 2;
    int g0 = blockIdx.x * 2 + gr;
    int iters = (n_nodes + gstride - 1) / gstride;

    for (int it = 0; it < iters; it++) {
        int i = g0 + it * gstride;
        __syncthreads();
        if (i < n_nodes) {
            ((float*)sF4[gr])[j] = feat[i * DIM + j];
            ((float*)sA4[gr])[j] = accf[i * DIM + j];
        }
        __syncthreads();
        if (i < n_nodes) {
            bool has = (g_offsets[i + 1] > g_offsets[i]);
            float accv = 0.f, loopv = 0.f;
            if (has) {
                #pragma unroll
                for (int kk = 0; kk < DIM / 4; kk++) {
                    float4 a4 = sA4[gr][kk];
                    float4 f4 = sF4[gr][kk];
                    accv  = fmaf(a4.x, wr[4 * kk + 0], accv);
                    accv  = fmaf(a4.y, wr[4 * kk + 1], accv);
                    accv  = fmaf(a4.z, wr[4 * kk + 2], accv);
                    accv  = fmaf(a4.w, wr[4 * kk + 3], accv);
                    loopv = fmaf(f4.x, wl[4 * kk + 0], loopv);
                    loopv = fmaf(f4.y, wl[4 * kk + 1], loopv);
                    loopv = fmaf(f4.z, wl[4 * kk + 2], loopv);
                    loopv = fmaf(f4.w, wl[4 * kk + 3], loopv);
                }
            } else {
                const float* sFp = (const float*)sF4[gr];
                #pragma unroll 8
                for (int k = 0; k < DIM; k++)
                    loopv = fmaf(sFp[k], evolve_w[k * DIM + j], loopv);
            }
            float nrm = norm[i];
            float nf = has ? accv * nrm : ((const float*)sF4[gr])[j] * nrm;
            out[i * DIM + j] = tanhf(nf + loopv);
        }
    }
}

// ---------------------------------------------------------------------------
// Launch
// Inputs (metadata order): feat, norm, edge_src, edge_dst, etype,
//                          W_rel, lin_w, lin_b, loop_w, evolve_loop_w
// ---------------------------------------------------------------------------
extern "C" void kernel_launch(void* const* d_in, const int* in_sizes, int n_in,
                              void* d_out, int out_size) {
    const float* feat     = (const float*)d_in[0];
    const float* norm     = (const float*)d_in[1];
    const int*   edge_src = (const int*)  d_in[2];
    const int*   edge_dst = (const int*)  d_in[3];
    // d_in[4] = etype: unused (same W_rel for every type)
    const float* W_rel    = (const float*)d_in[5];
    const float* lin_w    = (const float*)d_in[6];
    const float* lin_b    = (const float*)d_in[7];
    const float* loop_w   = (const float*)d_in[8];
    const float* evolve_w = (const float*)d_in[9];
    float*       out      = (float*)d_out;

    int n_nodes = in_sizes[1];
    int n_edges = in_sizes[2];
    if (n_nodes > N_NODES) n_nodes = N_NODES;
    if (n_edges > N_EDGES) n_edges = N_EDGES;

    int pq_blocks   = (n_nodes * 32 + 255) / 256;   // 6250
    int hist_blocks = (n_edges + 255) / 256;        // 6250
    int scan_blocks = (n_nodes + SCAN_B - 1) / SCAN_B;  // 98

    // 1) fused pq + histogram
    pq_hist_kernel<<<pq_blocks + hist_blocks, 256>>>(
        feat, lin_w, edge_dst, n_nodes, n_edges, pq_blocks);
    // 2) one-shot scan -> offsets + cursor
    fullscan_kernel<<<scan_blocks, SCAN_B>>>(n_nodes, n_edges);
    // 3) CSR build (+ re-zero deg for next replay)
    build_kernel<<<hist_blocks, 256>>>(edge_src, edge_dst, n_edges, n_nodes);
    // 4) gather: warp per node, grid-stride
    gather_kernel<<<1216, 256>>>((const float2*)feat, lin_b, n_nodes);
    // 5) finalize: W in registers, 456 blocks (152 SMs x 3)
    finalize_kernel<<<456, 128>>>(feat, norm, W_rel, loop_w, evolve_w, out, n_nodes);
}